// round 10
// baseline (speedup 1.0000x reference)
#include <cuda_runtime.h>
#include <cuda_fp16.h>
#include <cstdint>
#include <math.h>

// ---------------------------------------------------------------------------
// SimpleConvRNN fused kernel for GB300 (sm_103a) — round 10.
// mma.sync fp16, 512 thr / 16 warps = 4 out-groups x 4 px-groups(48px),
// named-barrier decoupled group pipelines, group-cooperative staging,
// zero-skip of L0 lower half when use_memory==0.
// ---------------------------------------------------------------------------

namespace {
constexpr int kB   = 32;
constexpr int kHW  = 6144;
constexpr int kTP  = 192;                   // pixels per tile (4 groups x 48)
constexpr int kTilesPerB = 32;
constexpr int kNTiles = kB * kTilesPerB;    // 1024
constexpr int kTHREADS = 512;

constexpr int kLDW  = 136;                  // W0/W1 pitch (halves)
constexpr int kLDW2 = 72;                   // W2 pitch (halves)
constexpr int kLDX  = 200;                  // xs pitch (halves) = 400B (25x16B)

constexpr int W0B = 0;
constexpr int W1B = W0B + 128 * kLDW * 2;   // 34816
constexpr int W2B = W1B + 128 * kLDW * 2;   // 69632
constexpr int X0B = W2B + 128 * kLDW2 * 2;  // 88064
constexpr int X1B = X0B + 128 * kLDX * 2;   // 139264
constexpr size_t SMEM_BYTES = X1B + 128 * kLDX * 2;  // 190464 B
}

__device__ __forceinline__ uint32_t smem_u32(const void* p) {
    uint32_t a;
    asm("{ .reg .u64 t; cvta.to.shared.u64 t, %1; cvt.u32.u64 %0, t; }"
        : "=r"(a) : "l"(p));
    return a;
}
__device__ __forceinline__ void ldsm4t(uint32_t* r, uint32_t addr) {
    asm volatile("ldmatrix.sync.aligned.m8n8.x4.trans.shared.b16 "
                 "{%0,%1,%2,%3}, [%4];"
                 : "=r"(r[0]), "=r"(r[1]), "=r"(r[2]), "=r"(r[3]) : "r"(addr));
}
__device__ __forceinline__ void mma16816(float c[4], const uint32_t* a,
                                         const uint32_t b0, const uint32_t b1) {
    asm volatile(
        "mma.sync.aligned.m16n8k16.row.col.f32.f16.f16.f32 "
        "{%0,%1,%2,%3}, {%4,%5,%6,%7}, {%8,%9}, {%0,%1,%2,%3};"
        : "+f"(c[0]), "+f"(c[1]), "+f"(c[2]), "+f"(c[3])
        : "r"(a[0]), "r"(a[1]), "r"(a[2]), "r"(a[3]), "r"(b0), "r"(b1));
}
__device__ __forceinline__ uint32_t h2pack(float a, float b) {
    __half2 h = __floats2half2_rn(a, b);
    return *(uint32_t*)&h;
}
__device__ __forceinline__ void st_half4(__half* p, float a, float b,
                                         float c, float d) {
    uint2 v;
    v.x = h2pack(a, b);
    v.y = h2pack(c, d);
    *(uint2*)p = v;
}
#define GBAR(pg) asm volatile("bar.sync %0, 128;" :: "r"(1 + (pg)) : "memory")

__device__ float g_xf[kB * 16];
__device__ int   g_use[kB];
__device__ int   g_midx[kB];

// ---------------------------------------------------------------------------
__global__ void prep_kernel(const float* __restrict__ prev_ext,
                            const float* __restrict__ cur_ext,
                            const int*   __restrict__ memory_idx,
                            const unsigned char* __restrict__ use_raw) {
    int b = threadIdx.x;
    if (b >= kB) return;

    const unsigned int* w32 = (const unsigned int*)use_raw;
    bool int_layout = true, float_layout = true;
    #pragma unroll
    for (int i = 0; i < 8; i++) {
        unsigned int v = w32[i];
        if (v != 0u && v != 1u)          int_layout = false;
        if (v != 0u && v != 0x3f800000u) float_layout = false;
    }
    int use;
    if (int_layout || float_layout) use = (w32[b] != 0u) ? 1 : 0;
    else                            use = use_raw[b] ? 1 : 0;
    g_use[b] = use;
    int m = memory_idx[b];
    g_midx[b] = m;

    float A[4][8];
    #pragma unroll
    for (int r = 0; r < 4; r++)
        #pragma unroll
        for (int c = 0; c < 4; c++) {
            A[r][c]     = use ? prev_ext[(size_t)m * 16 + r * 4 + c]
                              : (r == c ? 1.f : 0.f);
            A[r][c + 4] = (r == c) ? 1.f : 0.f;
        }
    for (int col = 0; col < 4; col++) {
        int piv = col;
        float best = fabsf(A[col][col]);
        for (int r = col + 1; r < 4; r++) {
            float v = fabsf(A[r][col]);
            if (v > best) { best = v; piv = r; }
        }
        if (piv != col)
            for (int j = 0; j < 8; j++) {
                float t = A[col][j]; A[col][j] = A[piv][j]; A[piv][j] = t;
            }
        float inv = 1.f / A[col][col];
        for (int j = 0; j < 8; j++) A[col][j] *= inv;
        for (int r = 0; r < 4; r++) {
            if (r == col) continue;
            float f = A[r][col];
            for (int j = 0; j < 8; j++) A[r][j] -= f * A[col][j];
        }
    }
    #pragma unroll
    for (int i = 0; i < 4; i++)
        #pragma unroll
        for (int j = 0; j < 4; j++) {
            float s = 0.f;
            #pragma unroll
            for (int k = 0; k < 4; k++)
                s += cur_ext[(size_t)b * 16 + i * 4 + k] * A[k][4 + j];
            g_xf[b * 16 + i * 4 + j] = s;
        }
}

// ---------------------------------------------------------------------------
// 32out x 48px layer slice, ksteps k-iterations (start fragment addrs given).
// Epilogue: bias + relu + fp16 -> STS into xw[out][px].
__device__ __forceinline__ void layer_gemm48(
    uint32_t aW, uint32_t aB, int ksteps, const float bl[4],
    uint32_t xw, int out0, int px0, int r, int col2)
{
    float c[2][6][4];
    #pragma unroll
    for (int m = 0; m < 2; m++)
        #pragma unroll
        for (int n = 0; n < 6; n++)
            #pragma unroll
            for (int j = 0; j < 4; j++) c[m][n][j] = 0.f;

    #pragma unroll 4
    for (int k = 0; k < ksteps; k++) {
        uint32_t a0[4], a1[4], b0[4], b1[4], b2[4];
        ldsm4t(a0, aW);
        ldsm4t(a1, aW + 32);
        ldsm4t(b0, aB);
        ldsm4t(b1, aB + 32);
        ldsm4t(b2, aB + 64);
        mma16816(c[0][0], a0, b0[0], b0[1]);
        mma16816(c[0][1], a0, b0[2], b0[3]);
        mma16816(c[0][2], a0, b1[0], b1[1]);
        mma16816(c[0][3], a0, b1[2], b1[3]);
        mma16816(c[0][4], a0, b2[0], b2[1]);
        mma16816(c[0][5], a0, b2[2], b2[3]);
        mma16816(c[1][0], a1, b0[0], b0[1]);
        mma16816(c[1][1], a1, b0[2], b0[3]);
        mma16816(c[1][2], a1, b1[0], b1[1]);
        mma16816(c[1][3], a1, b1[2], b1[3]);
        mma16816(c[1][4], a1, b2[0], b2[1]);
        mma16816(c[1][5], a1, b2[2], b2[3]);
        aW += 16 * kLDW * 2;
        aB += 16 * kLDX * 2;
    }

    #pragma unroll
    for (int m = 0; m < 2; m++) {
        float bhi = bl[2 * m], blo = bl[2 * m + 1];
        int row = out0 + 16 * m + r;
        #pragma unroll
        for (int n = 0; n < 6; n++) {
            const float* cc = c[m][n];
            uint32_t h01 = h2pack(fmaxf(cc[0] + bhi, 0.f),
                                  fmaxf(cc[1] + bhi, 0.f));
            uint32_t h23 = h2pack(fmaxf(cc[2] + blo, 0.f),
                                  fmaxf(cc[3] + blo, 0.f));
            uint32_t addr = xw + (uint32_t)(row * kLDX + px0 + 8 * n + col2) * 2;
            asm volatile("st.shared.b32 [%0], %1;" :: "r"(addr), "r"(h01));
            asm volatile("st.shared.b32 [%0], %1;"
                         :: "r"(addr + 8 * kLDX * 2), "r"(h23));
        }
    }
}

// ---------------------------------------------------------------------------
__global__ void __launch_bounds__(kTHREADS, 1)
fused_kernel(const float* __restrict__ img,
             const float* __restrict__ mem,
             const float* __restrict__ Ws,
             const float* __restrict__ bs,
             float* __restrict__ out) {
    extern __shared__ char smc[];
    const uint32_t sb = smem_u32(smc);
    __half* W0h = (__half*)(smc + W0B);
    __half* W1h = (__half*)(smc + W1B);
    __half* W2h = (__half*)(smc + W2B);
    __half* xs0 = (__half*)(smc + X0B);

    const int tid  = threadIdx.x;
    const int wid  = tid >> 5;
    const int lane = tid & 31;
    const int r    = lane >> 2;
    const int col2 = (lane & 3) * 2;

    // ---- one-time weight staging (transposed [k][out], fp16) ----
    for (int i = tid; i < 128 * 128; i += kTHREADS) {
        int o = i >> 7, k = i & 127;
        W0h[k * kLDW + o] = __float2half_rn(Ws[o * 128 + k]);
        W1h[k * kLDW + o] = __float2half_rn(Ws[16384 + o * 128 + k]);
    }
    for (int i = tid; i < 64 * 128; i += kTHREADS) {
        int o = i >> 7, k = i & 127;
        W2h[k * kLDW2 + o] = __float2half_rn(Ws[2 * 16384 + (64 + o) * 128 + k]);
    }

    // ---- warp tiling: og = out-group (32 ch), pg = px-group (48 px) ----
    const int og    = wid & 3;
    const int pg    = wid >> 2;                // 0..3
    const int out0  = og * 32;
    const int px0   = pg * 48;
    const int out20 = og * 16;
    const int gl    = og * 32 + lane;          // group-local id 0..127
    float bL0[4], bL1[4], bL2[2];
    #pragma unroll
    for (int j = 0; j < 4; j++) {
        bL0[j] = bs[out0 + r + 8 * j];
        bL1[j] = bs[128 + out0 + r + 8 * j];
    }
    bL2[0] = bs[256 + 64 + out20 + r];
    bL2[1] = bs[256 + 64 + out20 + r + 8];

    // ---- lane-derived ldmatrix base addresses ----
    const int lA_k = (lane & 7) + ((lane & 16) ? 8 : 0);
    const int lA_c = (lane & 8) ? 8 : 0;
    const int lB_k = (lane & 7) + ((lane & 8) ? 8 : 0);
    const int lB_c = (lane & 16) ? 8 : 0;

    const uint32_t aW0 = sb + W0B + (uint32_t)(lA_k * kLDW + out0 + lA_c) * 2;
    const uint32_t aW1 = sb + W1B + (uint32_t)(lA_k * kLDW + out0 + lA_c) * 2;
    const uint32_t aW2 = sb + W2B + (uint32_t)(lA_k * kLDW2 + out20 + lA_c) * 2;
    const uint32_t aB0 = sb + X0B + (uint32_t)(lB_k * kLDX + px0 + lB_c) * 2;
    const uint32_t aB1 = sb + X1B + (uint32_t)(lB_k * kLDX + px0 + lB_c) * 2;

    // staging item mapping: q -> (row = q/12, c4 = (q%12)*4) within 48 px
    const int sft_g  = gl / 12;                // FTL 4-ch group (gl < 96)
    const int sft_c4 = (gl % 12) * 4;

    __syncthreads();   // weights visible

    for (int t = blockIdx.x; t < kNTiles; t += gridDim.x) {
        const int b  = t >> 5;
        const int p0 = (t & 31) * kTP;
        const int useb = g_use[b];
        const int m    = g_midx[b];
        const int gpx0 = p0 + px0;

        // prefetch xf for FTL threads (hide LDG latency behind img staging)
        float xfv[16];
        if (useb && gl < 96) {
            #pragma unroll
            for (int j = 0; j < 16; j++) xfv[j] = g_xf[b * 16 + j];
        }

        GBAR(pg);   // S1: this group's prior-tile L2 done reading xs0

        // ---- group-cooperative staging of 48px slice into xs0 ----
        #pragma unroll
        for (int n = 0; n < 6; n++) {              // img -> rows 64..127
            int q  = gl + n * 128;                 // [0,768)
            int ch = q / 12, c4 = (q % 12) * 4;
            float4 v = *(const float4*)(img + (size_t)(b * 64 + ch) * kHW
                                        + gpx0 + c4);
            st_half4(xs0 + (64 + ch) * kLDX + px0 + c4, v.x, v.y, v.z, v.w);
        }
        if (useb) {
            #pragma unroll
            for (int n = 0; n < 3; n++) {          // mem -> rows 32..63
                int q  = gl + n * 128;             // [0,384)
                int ch = q / 12, c4 = (q % 12) * 4;
                float4 v = *(const float4*)(mem + (size_t)(m * 64 + 32 + ch) * kHW
                                            + gpx0 + c4);
                st_half4(xs0 + (32 + ch) * kLDX + px0 + c4, v.x, v.y, v.z, v.w);
            }
            if (gl < 96) {                         // FTL -> rows 0..31
                const float* mp = mem + (size_t)(m * 64 + 4 * sft_g) * kHW
                                + gpx0 + sft_c4;
                float4 v0 = *(const float4*)(mp);
                float4 v1 = *(const float4*)(mp + kHW);
                float4 v2 = *(const float4*)(mp + 2 * kHW);
                float4 v3 = *(const float4*)(mp + 3 * kHW);
                __half* xg = xs0 + (4 * sft_g) * kLDX + px0 + sft_c4;
                #pragma unroll
                for (int rr = 0; rr < 4; rr++) {
                    float a0 = xfv[rr*4+0], a1 = xfv[rr*4+1];
                    float a2 = xfv[rr*4+2], a3 = xfv[rr*4+3];
                    st_half4(xg + rr * kLDX,
                             a0*v0.x + a1*v1.x + a2*v2.x + a3*v3.x,
                             a0*v0.y + a1*v1.y + a2*v2.y + a3*v3.y,
                             a0*v0.z + a1*v1.z + a2*v2.z + a3*v3.z,
                             a0*v0.w + a1*v1.w + a2*v2.w + a3*v3.w);
                }
            }
        }
        // useb==0: rows 0..63 left unstaged; L0 skips k<64 entirely.
        GBAR(pg);   // S2: slice staged

        // ---- L0: read xs0, write xs1 (zero-skip lower half if !useb) ----
        if (useb)
            layer_gemm48(aW0, aB0, 8, bL0, sb + X1B, out0, px0, r, col2);
        else
            layer_gemm48(aW0 + 64 * kLDW * 2, aB0 + 64 * kLDX * 2, 4,
                         bL0, sb + X1B, out0, px0, r, col2);
        GBAR(pg);   // S3

        // ---- L1: read xs1, write xs0 ----
        layer_gemm48(aW1, aB1, 8, bL1, sb + X0B, out0, px0, r, col2);
        GBAR(pg);   // S4

        // ---- L2: read xs0, 16out x 48px, straight to gmem ----
        {
            float c[6][4];
            #pragma unroll
            for (int n = 0; n < 6; n++)
                #pragma unroll
                for (int j = 0; j < 4; j++) c[n][j] = 0.f;

            uint32_t aA = aW2, aB = aB0;
            #pragma unroll 4
            for (int k = 0; k < 8; k++) {
                uint32_t a0[4], b0[4], b1[4], b2[4];
                ldsm4t(a0, aA);
                ldsm4t(b0, aB);
                ldsm4t(b1, aB + 32);
                ldsm4t(b2, aB + 64);
                mma16816(c[0], a0, b0[0], b0[1]);
                mma16816(c[1], a0, b0[2], b0[3]);
                mma16816(c[2], a0, b1[0], b1[1]);
                mma16816(c[3], a0, b1[2], b1[3]);
                mma16816(c[4], a0, b2[0], b2[1]);
                mma16816(c[5], a0, b2[2], b2[3]);
                aA += 16 * kLDW2 * 2;
                aB += 16 * kLDX * 2;
            }
            float* obase = out + (size_t)(b * 64 + out20 + r) * kHW
                         + gpx0 + col2;
            #pragma unroll
            for (int n = 0; n < 6; n++) {
                float2 v01 = make_float2(c[n][0] + bL2[0], c[n][1] + bL2[0]);
                float2 v23 = make_float2(c[n][2] + bL2[1], c[n][3] + bL2[1]);
                *(float2*)(obase + 8 * n)                   = v01;
                *(float2*)(obase + 8 * n + (size_t)8 * kHW) = v23;
            }
        }
        // loop-head S1 guards xs0 restaging for this group
    }
}

// ---------------------------------------------------------------------------
extern "C" void kernel_launch(void* const* d_in, const int* in_sizes, int n_in,
                              void* d_out, int out_size) {
    const float* img      = (const float*)d_in[0];
    const float* mem      = (const float*)d_in[1];
    const float* prev_ext = (const float*)d_in[2];
    const float* cur_ext  = (const float*)d_in[3];
    const int*   midx     = (const int*)d_in[4];
    const unsigned char* use_raw = (const unsigned char*)d_in[5];
    const float* Ws       = (const float*)d_in[6];
    const float* bs       = (const float*)d_in[7];
    float*       out      = (float*)d_out;

    static int nsm = 0;
    if (nsm == 0) {
        int dev = 0;
        cudaGetDevice(&dev);
        cudaDeviceGetAttribute(&nsm, cudaDevAttrMultiProcessorCount, dev);
        if (nsm <= 0) nsm = 148;
        cudaFuncSetAttribute(fused_kernel,
                             cudaFuncAttributeMaxDynamicSharedMemorySize,
                             (int)SMEM_BYTES);
    }

    prep_kernel<<<1, 32>>>(prev_ext, cur_ext, midx, use_raw);
    fused_kernel<<<nsm, kTHREADS, SMEM_BYTES>>>(img, mem, Ws, bs, out);
}

// round 11
// speedup vs baseline: 1.0478x; 1.0478x over previous
#include <cuda_runtime.h>
#include <cuda_fp16.h>
#include <cstdint>
#include <math.h>

// ---------------------------------------------------------------------------
// SimpleConvRNN fused kernel for GB300 (sm_103a) — round 11.
// R9 architecture (768 thr, 24 warps = 4 out-groups x 6 px-groups, mma.sync
// fp16 32x32 warp tiles, named-barrier decoupled group pipelines) + R10's
// zero-skip: when use_memory==0, rows 0..63 are exactly zero -> skip their
// staging and run L0 with k = 64..127 only.
// ---------------------------------------------------------------------------

namespace {
constexpr int kB   = 32;
constexpr int kHW  = 6144;
constexpr int kTP  = 192;                   // pixels per tile (6 px-groups x 32)
constexpr int kTilesPerB = 32;
constexpr int kNTiles = kB * kTilesPerB;    // 1024
constexpr int kTHREADS = 768;

constexpr int kLDW  = 136;                  // W0/W1 pitch (halves)
constexpr int kLDW2 = 72;                   // W2 pitch (halves)
constexpr int kLDX  = 200;                  // xs pitch (halves)

constexpr int W0B = 0;
constexpr int W1B = W0B + 128 * kLDW * 2;   // 34816
constexpr int W2B = W1B + 128 * kLDW * 2;   // 69632
constexpr int X0B = W2B + 128 * kLDW2 * 2;  // 88064
constexpr int X1B = X0B + 128 * kLDX * 2;   // 139264
constexpr size_t SMEM_BYTES = X1B + 128 * kLDX * 2;  // 190464 B
}

__device__ __forceinline__ uint32_t smem_u32(const void* p) {
    uint32_t a;
    asm("{ .reg .u64 t; cvta.to.shared.u64 t, %1; cvt.u32.u64 %0, t; }"
        : "=r"(a) : "l"(p));
    return a;
}
__device__ __forceinline__ void ldsm4t(uint32_t* r, uint32_t addr) {
    asm volatile("ldmatrix.sync.aligned.m8n8.x4.trans.shared.b16 "
                 "{%0,%1,%2,%3}, [%4];"
                 : "=r"(r[0]), "=r"(r[1]), "=r"(r[2]), "=r"(r[3]) : "r"(addr));
}
__device__ __forceinline__ void mma16816(float c[4], const uint32_t* a,
                                         const uint32_t b0, const uint32_t b1) {
    asm volatile(
        "mma.sync.aligned.m16n8k16.row.col.f32.f16.f16.f32 "
        "{%0,%1,%2,%3}, {%4,%5,%6,%7}, {%8,%9}, {%0,%1,%2,%3};"
        : "+f"(c[0]), "+f"(c[1]), "+f"(c[2]), "+f"(c[3])
        : "r"(a[0]), "r"(a[1]), "r"(a[2]), "r"(a[3]), "r"(b0), "r"(b1));
}
__device__ __forceinline__ uint32_t h2pack(float a, float b) {
    __half2 h = __floats2half2_rn(a, b);
    return *(uint32_t*)&h;
}
__device__ __forceinline__ void st_half4(__half* p, float a, float b,
                                         float c, float d) {
    uint2 v;
    v.x = h2pack(a, b);
    v.y = h2pack(c, d);
    *(uint2*)p = v;
}
#define GBAR(pg) asm volatile("bar.sync %0, 128;" :: "r"(1 + (pg)) : "memory")

__device__ float g_xf[kB * 16];
__device__ int   g_use[kB];
__device__ int   g_midx[kB];

// ---------------------------------------------------------------------------
__global__ void prep_kernel(const float* __restrict__ prev_ext,
                            const float* __restrict__ cur_ext,
                            const int*   __restrict__ memory_idx,
                            const unsigned char* __restrict__ use_raw) {
    int b = threadIdx.x;
    if (b >= kB) return;

    const unsigned int* w32 = (const unsigned int*)use_raw;
    bool int_layout = true, float_layout = true;
    #pragma unroll
    for (int i = 0; i < 8; i++) {
        unsigned int v = w32[i];
        if (v != 0u && v != 1u)          int_layout = false;
        if (v != 0u && v != 0x3f800000u) float_layout = false;
    }
    int use;
    if (int_layout || float_layout) use = (w32[b] != 0u) ? 1 : 0;
    else                            use = use_raw[b] ? 1 : 0;
    g_use[b] = use;
    int m = memory_idx[b];
    g_midx[b] = m;

    float A[4][8];
    #pragma unroll
    for (int r = 0; r < 4; r++)
        #pragma unroll
        for (int c = 0; c < 4; c++) {
            A[r][c]     = use ? prev_ext[(size_t)m * 16 + r * 4 + c]
                              : (r == c ? 1.f : 0.f);
            A[r][c + 4] = (r == c) ? 1.f : 0.f;
        }
    for (int col = 0; col < 4; col++) {
        int piv = col;
        float best = fabsf(A[col][col]);
        for (int r = col + 1; r < 4; r++) {
            float v = fabsf(A[r][col]);
            if (v > best) { best = v; piv = r; }
        }
        if (piv != col)
            for (int j = 0; j < 8; j++) {
                float t = A[col][j]; A[col][j] = A[piv][j]; A[piv][j] = t;
            }
        float inv = 1.f / A[col][col];
        for (int j = 0; j < 8; j++) A[col][j] *= inv;
        for (int r = 0; r < 4; r++) {
            if (r == col) continue;
            float f = A[r][col];
            for (int j = 0; j < 8; j++) A[r][j] -= f * A[col][j];
        }
    }
    #pragma unroll
    for (int i = 0; i < 4; i++)
        #pragma unroll
        for (int j = 0; j < 4; j++) {
            float s = 0.f;
            #pragma unroll
            for (int k = 0; k < 4; k++)
                s += cur_ext[(size_t)b * 16 + i * 4 + k] * A[k][4 + j];
            g_xf[b * 16 + i * 4 + j] = s;
        }
}

// ---------------------------------------------------------------------------
// 32out x 32px layer slice, ksteps k-iterations. Epilogue bias+relu+fp16 -> STS.
__device__ __forceinline__ void layer_gemm32(
    uint32_t aW, uint32_t aB, int ksteps, const float bl[4],
    uint32_t xw, int out0, int pxcol, int r, int col2)
{
    float c[8][4];
    #pragma unroll
    for (int i = 0; i < 8; i++)
        #pragma unroll
        for (int j = 0; j < 4; j++) c[i][j] = 0.f;

    #pragma unroll 4
    for (int k = 0; k < ksteps; k++) {
        uint32_t a0[4], a1[4], b0[4], b1[4];
        ldsm4t(a0, aW);
        ldsm4t(a1, aW + 32);
        ldsm4t(b0, aB);
        ldsm4t(b1, aB + 32);
        mma16816(c[0], a0, b0[0], b0[1]);
        mma16816(c[1], a0, b0[2], b0[3]);
        mma16816(c[2], a0, b1[0], b1[1]);
        mma16816(c[3], a0, b1[2], b1[3]);
        mma16816(c[4], a1, b0[0], b0[1]);
        mma16816(c[5], a1, b0[2], b0[3]);
        mma16816(c[6], a1, b1[0], b1[1]);
        mma16816(c[7], a1, b1[2], b1[3]);
        aW += 16 * kLDW * 2;
        aB += 16 * kLDX * 2;
    }

    #pragma unroll
    for (int f = 0; f < 2; f++) {
        float bhi = bl[2 * f], blo = bl[2 * f + 1];
        int row = out0 + 16 * f + r;
        #pragma unroll
        for (int p = 0; p < 4; p++) {
            const float* cc = c[f * 4 + p];
            uint32_t h01 = h2pack(fmaxf(cc[0] + bhi, 0.f),
                                  fmaxf(cc[1] + bhi, 0.f));
            uint32_t h23 = h2pack(fmaxf(cc[2] + blo, 0.f),
                                  fmaxf(cc[3] + blo, 0.f));
            uint32_t addr = xw + (uint32_t)(row * kLDX + pxcol + 8 * p + col2) * 2;
            asm volatile("st.shared.b32 [%0], %1;" :: "r"(addr), "r"(h01));
            asm volatile("st.shared.b32 [%0], %1;"
                         :: "r"(addr + 8 * kLDX * 2), "r"(h23));
        }
    }
}

// ---------------------------------------------------------------------------
__global__ void __launch_bounds__(kTHREADS, 1)
fused_kernel(const float* __restrict__ img,
             const float* __restrict__ mem,
             const float* __restrict__ Ws,
             const float* __restrict__ bs,
             float* __restrict__ out) {
    extern __shared__ char smc[];
    const uint32_t sb = smem_u32(smc);
    __half* W0h = (__half*)(smc + W0B);
    __half* W1h = (__half*)(smc + W1B);
    __half* W2h = (__half*)(smc + W2B);
    __half* xs0 = (__half*)(smc + X0B);

    const int tid  = threadIdx.x;
    const int wid  = tid >> 5;
    const int lane = tid & 31;
    const int r    = lane >> 2;
    const int col2 = (lane & 3) * 2;

    // ---- one-time weight staging (transposed [k][out], fp16) ----
    for (int i = tid; i < 128 * 128; i += kTHREADS) {
        int o = i >> 7, k = i & 127;
        W0h[k * kLDW + o] = __float2half_rn(Ws[o * 128 + k]);
        W1h[k * kLDW + o] = __float2half_rn(Ws[16384 + o * 128 + k]);
    }
    for (int i = tid; i < 64 * 128; i += kTHREADS) {
        int o = i >> 7, k = i & 127;
        W2h[k * kLDW2 + o] = __float2half_rn(Ws[2 * 16384 + (64 + o) * 128 + k]);
    }

    // ---- warp tiling: og = out-group (32 ch), pg = px-group (32 px) ----
    const int og    = wid & 3;
    const int pg    = wid >> 2;                // 0..5
    const int out0  = og * 32;
    const int px0   = pg * 32;
    const int out20 = og * 16;
    float bL0[4], bL1[4], bL2[2];
    #pragma unroll
    for (int j = 0; j < 4; j++) {
        bL0[j] = bs[out0 + r + 8 * j];
        bL1[j] = bs[128 + out0 + r + 8 * j];
    }
    bL2[0] = bs[256 + 64 + out20 + r];
    bL2[1] = bs[256 + 64 + out20 + r + 8];

    // ---- lane-derived ldmatrix base addresses ----
    const int lA_k = (lane & 7) + ((lane & 16) ? 8 : 0);
    const int lA_c = (lane & 8) ? 8 : 0;
    const int lB_k = (lane & 7) + ((lane & 8) ? 8 : 0);
    const int lB_c = (lane & 16) ? 8 : 0;

    const uint32_t aW0 = sb + W0B + (uint32_t)(lA_k * kLDW + out0 + lA_c) * 2;
    const uint32_t aW1 = sb + W1B + (uint32_t)(lA_k * kLDW + out0 + lA_c) * 2;
    const uint32_t aW2 = sb + W2B + (uint32_t)(lA_k * kLDW2 + out20 + lA_c) * 2;
    const uint32_t aB0 = sb + X0B + (uint32_t)(lB_k * kLDX + px0 + lB_c) * 2;
    const uint32_t aB1 = sb + X1B + (uint32_t)(lB_k * kLDX + px0 + lB_c) * 2;

    // staging lane mapping: 4 px per lane, 8 channels per lane
    const int spx = (lane & 7) << 2;           // px offset within group: 0..28
    const int sch = (lane >> 3) << 3;          // ch offset within 32: 0,8,16,24

    __syncthreads();   // weights visible to all groups

    for (int t = blockIdx.x; t < kNTiles; t += gridDim.x) {
        const int b  = t >> 5;
        const int p0 = (t & 31) * kTP;
        const int useb = g_use[b];
        const int m    = g_midx[b];

        GBAR(pg);   // S1: this group's prior-tile L2 done reading xs0

        // ---- stage this warp's 32ch x 32px slice into xs0 ----
        // (og 0/1 = rows 0..63: skipped entirely when !useb -> L0 zero-skip)
        if (og >= 2) {                                         // img channels
            const int gpx = p0 + px0 + spx;
            __half* xd = xs0 + (64 + (og - 2) * 32 + sch) * kLDX + px0 + spx;
            const float* base =
                img + (size_t)(b * 64 + (og - 2) * 32 + sch) * kHW + gpx;
            #pragma unroll
            for (int c = 0; c < 8; c++) {
                float4 v = *(const float4*)(base + (size_t)c * kHW);
                st_half4(xd + c * kLDX, v.x, v.y, v.z, v.w);
            }
        } else if (useb) {
            const int gpx = p0 + px0 + spx;
            if (og == 1) {                                     // mem ch 32..63
                __half* xd = xs0 + (32 + sch) * kLDX + px0 + spx;
                const float* base =
                    mem + (size_t)(m * 64 + 32 + sch) * kHW + gpx;
                #pragma unroll
                for (int c = 0; c < 8; c++) {
                    float4 v = *(const float4*)(base + (size_t)c * kHW);
                    st_half4(xd + c * kLDX, v.x, v.y, v.z, v.w);
                }
            } else {                                           // FTL ch 0..31
                float xfv[16];
                #pragma unroll
                for (int j = 0; j < 16; j++) xfv[j] = g_xf[b * 16 + j];
                #pragma unroll
                for (int gi = 0; gi < 2; gi++) {
                    int g = (sch >> 2) + gi;                   // 4-ch group 0..7
                    const float* mp =
                        mem + (size_t)(m * 64 + 4 * g) * kHW + gpx;
                    float4 v0 = *(const float4*)(mp);
                    float4 v1 = *(const float4*)(mp + kHW);
                    float4 v2 = *(const float4*)(mp + 2 * kHW);
                    float4 v3 = *(const float4*)(mp + 3 * kHW);
                    __half* xg = xs0 + (4 * g) * kLDX + px0 + spx;
                    #pragma unroll
                    for (int rr = 0; rr < 4; rr++) {
                        float a0 = xfv[rr*4+0], a1 = xfv[rr*4+1];
                        float a2 = xfv[rr*4+2], a3 = xfv[rr*4+3];
                        st_half4(xg + rr * kLDX,
                                 a0*v0.x + a1*v1.x + a2*v2.x + a3*v3.x,
                                 a0*v0.y + a1*v1.y + a2*v2.y + a3*v3.y,
                                 a0*v0.z + a1*v1.z + a2*v2.z + a3*v3.z,
                                 a0*v0.w + a1*v1.w + a2*v2.w + a3*v3.w);
                    }
                }
            }
        }
        GBAR(pg);   // S2: group's xs0 slice staged

        // ---- L0: read xs0, write xs1 (k-skip lower half when !useb) ----
        if (useb)
            layer_gemm32(aW0, aB0, 8, bL0, sb + X1B, out0, px0, r, col2);
        else
            layer_gemm32(aW0 + 64 * kLDW * 2, aB0 + 64 * kLDX * 2, 4,
                         bL0, sb + X1B, out0, px0, r, col2);
        GBAR(pg);   // S3

        // ---- L1: read xs1, write xs0 ----
        layer_gemm32(aW1, aB1, 8, bL1, sb + X0B, out0, px0, r, col2);
        GBAR(pg);   // S4

        // ---- L2: read xs0, 16out x 32px, straight to gmem ----
        {
            float c[4][4];
            #pragma unroll
            for (int i = 0; i < 4; i++)
                #pragma unroll
                for (int j = 0; j < 4; j++) c[i][j] = 0.f;

            uint32_t aA = aW2, aB = aB0;
            #pragma unroll 4
            for (int k = 0; k < 8; k++) {
                uint32_t a0[4], b0[4], b1[4];
                ldsm4t(a0, aA);
                ldsm4t(b0, aB);
                ldsm4t(b1, aB + 32);
                mma16816(c[0], a0, b0[0], b0[1]);
                mma16816(c[1], a0, b0[2], b0[3]);
                mma16816(c[2], a0, b1[0], b1[1]);
                mma16816(c[3], a0, b1[2], b1[3]);
                aA += 16 * kLDW2 * 2;
                aB += 16 * kLDX * 2;
            }
            float* obase = out + (size_t)(b * 64 + out20 + r) * kHW
                         + p0 + px0 + col2;
            #pragma unroll
            for (int p = 0; p < 4; p++) {
                float2 v01 = make_float2(c[p][0] + bL2[0], c[p][1] + bL2[0]);
                float2 v23 = make_float2(c[p][2] + bL2[1], c[p][3] + bL2[1]);
                *(float2*)(obase + 8 * p)                   = v01;
                *(float2*)(obase + 8 * p + (size_t)8 * kHW) = v23;
            }
        }
        // loop-head S1 guards xs0 restaging for this group
    }
}

// ---------------------------------------------------------------------------
extern "C" void kernel_launch(void* const* d_in, const int* in_sizes, int n_in,
                              void* d_out, int out_size) {
    const float* img      = (const float*)d_in[0];
    const float* mem      = (const float*)d_in[1];
    const float* prev_ext = (const float*)d_in[2];
    const float* cur_ext  = (const float*)d_in[3];
    const int*   midx     = (const int*)d_in[4];
    const unsigned char* use_raw = (const unsigned char*)d_in[5];
    const float* Ws       = (const float*)d_in[6];
    const float* bs       = (const float*)d_in[7];
    float*       out      = (float*)d_out;

    static int nsm = 0;
    if (nsm == 0) {
        int dev = 0;
        cudaGetDevice(&dev);
        cudaDeviceGetAttribute(&nsm, cudaDevAttrMultiProcessorCount, dev);
        if (nsm <= 0) nsm = 148;
        cudaFuncSetAttribute(fused_kernel,
                             cudaFuncAttributeMaxDynamicSharedMemorySize,
                             (int)SMEM_BYTES);
    }

    prep_kernel<<<1, 32>>>(prev_ext, cur_ext, midx, use_raw);
    fused_kernel<<<nsm, kTHREADS, SMEM_BYTES>>>(img, mem, Ws, bs, out);
}